// round 11
// baseline (speedup 1.0000x reference)
#include <cuda_runtime.h>
#include <cuda_bf16.h>
#include <cstdint>
#include <cstdio>

// Shapes (confirmed): B=4, T=1024, S=32, D=512; output = real part, fp32.
#define BT    4096
#define DIM   512
#define DIM2  1024
#define SLOTS 32

__device__ float g_Q [BT * DIM];
__device__ float g_Qk[BT * DIM2];
__device__ float g_wH[BT * DIM2];

__device__ __forceinline__ unsigned tf32cvt(float f)
{
    unsigned r;
    asm("cvt.rna.tf32.f32 %0, %1;" : "=r"(r) : "f"(f));
    return r;
}

// ---------------------------------------------------------------------------
// TF32 GEMM: CTA tile 64x64, 128 threads (4 warps 2x2), warp tile 32x32
// (2m x 4n m16n8k8 mma), K-tile 16, register-prefetch double buffering,
// conflict-free padded smem (row stride 72).
// ASRC: 1 = concat(A=cur_r, A2=cur_i) rows of 512+512; 2 = g_Q; 3 = g_wH
// BMODE: 0 = B row-major [K x Bstride]; 1 = B is [N x K] (use B^T)
// EPI: 0 = C = (acc + bias?) * (rowscale? basescale*rowscale[m] : 1)
//      1 = real epilogue: C[m*512+n] = cur_r[m*512+n] + 0.1*(acc + bias[n])
// CDST: 0 = g_Q, 1 = g_Qk, 2 = external C
// ---------------------------------------------------------------------------
template<int ASRC, int BMODE, int EPI, int CDST>
__global__ __launch_bounds__(128)
void gemm_t(const float* __restrict__ A, const float* __restrict__ A2,
            const float* __restrict__ B, int Bstride,
            const float* __restrict__ bias,
            const float* __restrict__ rowscale, float basescale,
            const float* __restrict__ cur_r,
            float* __restrict__ Cext,
            int M, int N, int K)
{
    __shared__ unsigned As[16][72];   // [k][m], stride 72 -> banks 8k+m
    __shared__ unsigned Bs[16][72];   // [k][n]

    const float* Aint = (ASRC == 2) ? g_Q : (ASRC == 3) ? g_wH : nullptr;
    float*       C    = (CDST == 0) ? g_Q : (CDST == 1) ? g_Qk : Cext;

    const int tid  = threadIdx.x;
    const int lane = tid & 31;
    const int wid  = tid >> 5;
    const int wm   = wid & 1;
    const int wn   = wid >> 1;
    const int grp  = lane >> 2;
    const int tig  = lane & 3;
    const int bm   = blockIdx.y * 64;
    const int bn0  = blockIdx.x * 64;

    float acc[2][4][4];
#pragma unroll
    for (int a = 0; a < 2; a++)
#pragma unroll
        for (int b = 0; b < 4; b++)
#pragma unroll
            for (int c = 0; c < 4; c++) acc[a][b][c] = 0.f;

    // Loader mapping: row = tid%64, k-chunk = (tid/64)*8 (conflict-free STS)
    const int lrow = tid & 63;
    const int lk   = (tid >> 6) * 8;

    float4 a0r, a1r, b0r, b1r;

    // --- LDG helpers (emitted inline twice: prologue + loop prefetch) ---
    auto ldgA = [&](int k0) {
        const long long m = bm + lrow;
        const long long k = k0 + lk;
        if (ASRC == 1) {
            if (k < 512) {
                a0r = *(const float4*)(A + m * 512 + k);
                a1r = *(const float4*)(A + m * 512 + k + 4);
            } else {
                a0r = *(const float4*)(A2 + m * 512 + (k - 512));
                a1r = *(const float4*)(A2 + m * 512 + (k - 512) + 4);
            }
        } else {
            a0r = *(const float4*)(Aint + m * (long long)K + k);
            a1r = *(const float4*)(Aint + m * (long long)K + k + 4);
        }
    };
    auto ldgB = [&](int k0) {
        if (BMODE == 0) {
            // 16 k-rows x 64 n: thread -> k = tid/8 (0..15), n = (tid%8)*8
            const long long k = k0 + (tid >> 3);
            const long long n = bn0 + (tid & 7) * 8;
            b0r = *(const float4*)(B + k * (long long)Bstride + n);
            b1r = *(const float4*)(B + k * (long long)Bstride + n + 4);
        } else {
            // B is [N x K]: row n = bn0+lrow, k chunk lk
            const long long n = bn0 + lrow;
            const long long k = k0 + lk;
            b0r = *(const float4*)(B + n * (long long)K + k);
            b1r = *(const float4*)(B + n * (long long)K + k + 4);
        }
    };
    auto stsAB = [&]() {
        As[lk + 0][lrow] = tf32cvt(a0r.x);
        As[lk + 1][lrow] = tf32cvt(a0r.y);
        As[lk + 2][lrow] = tf32cvt(a0r.z);
        As[lk + 3][lrow] = tf32cvt(a0r.w);
        As[lk + 4][lrow] = tf32cvt(a1r.x);
        As[lk + 5][lrow] = tf32cvt(a1r.y);
        As[lk + 6][lrow] = tf32cvt(a1r.z);
        As[lk + 7][lrow] = tf32cvt(a1r.w);
        if (BMODE == 0) {
            const int k = tid >> 3;
            const int n = (tid & 7) * 8;
            Bs[k][n + 0] = tf32cvt(b0r.x);
            Bs[k][n + 1] = tf32cvt(b0r.y);
            Bs[k][n + 2] = tf32cvt(b0r.z);
            Bs[k][n + 3] = tf32cvt(b0r.w);
            Bs[k][n + 4] = tf32cvt(b1r.x);
            Bs[k][n + 5] = tf32cvt(b1r.y);
            Bs[k][n + 6] = tf32cvt(b1r.z);
            Bs[k][n + 7] = tf32cvt(b1r.w);
        } else {
            Bs[lk + 0][lrow] = tf32cvt(b0r.x);
            Bs[lk + 1][lrow] = tf32cvt(b0r.y);
            Bs[lk + 2][lrow] = tf32cvt(b0r.z);
            Bs[lk + 3][lrow] = tf32cvt(b0r.w);
            Bs[lk + 4][lrow] = tf32cvt(b1r.x);
            Bs[lk + 5][lrow] = tf32cvt(b1r.y);
            Bs[lk + 6][lrow] = tf32cvt(b1r.z);
            Bs[lk + 7][lrow] = tf32cvt(b1r.w);
        }
    };

    ldgA(0);
    ldgB(0);

    for (int k0 = 0; k0 < K; k0 += 16) {
        stsAB();
        __syncthreads();
        if (k0 + 16 < K) {          // prefetch next tile during mma
            ldgA(k0 + 16);
            ldgB(k0 + 16);
        }

#pragma unroll
        for (int k8 = 0; k8 < 16; k8 += 8) {
            unsigned af[2][4];
#pragma unroll
            for (int mt = 0; mt < 2; mt++) {
                const int r = wm * 32 + mt * 16 + grp;
                af[mt][0] = As[k8 + tig    ][r];
                af[mt][1] = As[k8 + tig    ][r + 8];
                af[mt][2] = As[k8 + tig + 4][r];
                af[mt][3] = As[k8 + tig + 4][r + 8];
            }
            unsigned bf[4][2];
#pragma unroll
            for (int nt = 0; nt < 4; nt++) {
                const int n = wn * 32 + nt * 8 + grp;
                bf[nt][0] = Bs[k8 + tig    ][n];
                bf[nt][1] = Bs[k8 + tig + 4][n];
            }
#pragma unroll
            for (int mt = 0; mt < 2; mt++)
#pragma unroll
                for (int nt = 0; nt < 4; nt++)
                    asm volatile(
                        "mma.sync.aligned.m16n8k8.row.col.f32.tf32.tf32.f32 "
                        "{%0,%1,%2,%3}, {%4,%5,%6,%7}, {%8,%9}, {%0,%1,%2,%3};"
                        : "+f"(acc[mt][nt][0]), "+f"(acc[mt][nt][1]),
                          "+f"(acc[mt][nt][2]), "+f"(acc[mt][nt][3])
                        : "r"(af[mt][0]), "r"(af[mt][1]),
                          "r"(af[mt][2]), "r"(af[mt][3]),
                          "r"(bf[nt][0]), "r"(bf[nt][1]));
        }
        __syncthreads();
    }

    // --- epilogue ---
#pragma unroll
    for (int mt = 0; mt < 2; mt++) {
#pragma unroll
        for (int half = 0; half < 2; half++) {
            const long long m = bm + wm * 32 + mt * 16 + grp + half * 8;
            float rs = 1.f;
            if (EPI == 0 && rowscale != nullptr)
                rs = basescale * __ldg(rowscale + m);
#pragma unroll
            for (int nt = 0; nt < 4; nt++) {
                const long long n = bn0 + wn * 32 + nt * 8 + 2 * tig;
                float v0 = acc[mt][nt][half * 2 + 0];
                float v1 = acc[mt][nt][half * 2 + 1];
                if (bias != nullptr) {
                    v0 += __ldg(bias + n);
                    v1 += __ldg(bias + n + 1);
                }
                if (EPI == 0) {
                    C[m * N + n]     = v0 * rs;
                    C[m * N + n + 1] = v1 * rs;
                } else {
                    const long long f = m * 512 + n;
                    C[f]     = __ldg(cur_r + f)     + 0.1f * v0;
                    C[f + 1] = __ldg(cur_r + f + 1) + 0.1f * v1;
                }
            }
        }
    }
}

// ---------------------------------------------------------------------------
// Warp-specialized streaming attention (unchanged, known-good).
// ---------------------------------------------------------------------------
__global__ __launch_bounds__(256)
void attn_f(const float* __restrict__ hr, const float* __restrict__ hi)
{
    __shared__ __align__(16) float shQ[DIM2];
    __shared__ __align__(16) float shAcc[8][8][32][4];
    __shared__ float shM[8], shL[8];

    const int bt = blockIdx.x;
    const int w  = threadIdx.x >> 5;
    const int c  = threadIdx.x & 31;

    {
        const float* q = g_Qk + (size_t)bt * DIM2;
        *(float4*)&shQ[threadIdx.x * 4] = *(const float4*)(q + threadIdx.x * 4);
    }
    __syncthreads();

    const float* pr = hr + (size_t)bt * (SLOTS * 512) + 4 * c;
    const float* pi = hi + (size_t)bt * (SLOTS * 512) + 4 * c;

    float m = -1e30f, l = 0.f;
    float4 acc[8];
#pragma unroll
    for (int k = 0; k < 8; k++) acc[k] = make_float4(0.f, 0.f, 0.f, 0.f);

#pragma unroll
    for (int si = 0; si < 4; si++) {
        const int s = w + si * 8;
        float4 h[8];
#pragma unroll
        for (int k = 0; k < 4; k++)
            h[k] = *(const float4*)(pr + (size_t)s * 512 + k * 128);
#pragma unroll
        for (int k = 0; k < 4; k++)
            h[k + 4] = *(const float4*)(pi + (size_t)s * 512 + k * 128);

        float p = 0.f;
#pragma unroll
        for (int k = 0; k < 8; k++) {
            const float4 q = *(const float4*)&shQ[k * 128 + 4 * c];
            p += h[k].x * q.x + h[k].y * q.y + h[k].z * q.z + h[k].w * q.w;
        }
#pragma unroll
        for (int off = 16; off; off >>= 1)
            p += __shfl_xor_sync(0xffffffffu, p, off);

        const float mn = fmaxf(m, p);
        const float cf = __expf(m - mn);
        const float pw = __expf(p - mn);
        l = l * cf + pw;
#pragma unroll
        for (int k = 0; k < 8; k++) {
            acc[k].x = acc[k].x * cf + pw * h[k].x;
            acc[k].y = acc[k].y * cf + pw * h[k].y;
            acc[k].z = acc[k].z * cf + pw * h[k].z;
            acc[k].w = acc[k].w * cf + pw * h[k].w;
        }
        m = mn;
    }

    if (c == 0) { shM[w] = m; shL[w] = l; }
    __syncthreads();
    float M = -1e30f;
#pragma unroll
    for (int i = 0; i < 8; i++) M = fmaxf(M, shM[i]);
    float L = 0.f;
#pragma unroll
    for (int i = 0; i < 8; i++) L += shL[i] * __expf(shM[i] - M);
    const float myE = __expf(m - M);

#pragma unroll
    for (int k = 0; k < 8; k++) {
        float4 v = acc[k];
        v.x *= myE; v.y *= myE; v.z *= myE; v.w *= myE;
        *(float4*)&shAcc[w][k][c][0] = v;
    }
    __syncthreads();

    const float invL = 1.f / L;
    float4 sum = make_float4(0.f, 0.f, 0.f, 0.f);
#pragma unroll
    for (int sw = 0; sw < 8; sw++) {
        const float4 v = *(const float4*)&shAcc[sw][w][c][0];
        sum.x += v.x; sum.y += v.y; sum.z += v.z; sum.w += v.w;
    }
    sum.x *= invL; sum.y *= invL; sum.z *= invL; sum.w *= invL;
    *(float4*)&g_wH[(size_t)bt * DIM2 + w * 128 + 4 * c] = sum;
}

// ---------------------------------------------------------------------------
// Host-side staged diagnostics (only on the non-captured correctness call).
// ---------------------------------------------------------------------------
static bool kl_capturing()
{
    cudaStreamCaptureStatus st = cudaStreamCaptureStatusNone;
    cudaError_t e = cudaStreamIsCapturing((cudaStream_t)0, &st);
    if (e != cudaSuccess) { (void)cudaGetLastError(); return true; }
    return st != cudaStreamCaptureStatusNone;
}
static cudaError_t kl_poll()
{
    cudaEvent_t ev;
    if (cudaEventCreateWithFlags(&ev, cudaEventDisableTiming) != cudaSuccess)
        return cudaGetLastError();
    cudaEventRecord(ev, (cudaStream_t)0);
    cudaError_t e;
    do { e = cudaEventQuery(ev); } while (e == cudaErrorNotReady);
    cudaEventDestroy(ev);
    return e;
}
static void kl_stage(bool diag, const char* name, bool* dead)
{
    if (!diag || *dead) return;
    cudaError_t e = kl_poll();
    if (e != cudaSuccess) {
        fprintf(stderr, "[KLDIAG] stage %s -> %s\n", name, cudaGetErrorString(e));
        *dead = true;
    }
}

// ---------------------------------------------------------------------------
extern "C" void kernel_launch(void* const* d_in, const int* in_sizes, int n_in,
                              void* d_out, int out_size)
{
    const bool diag = !kl_capturing();
    if (n_in < 11) return;

    // Confirmed insertion order, all fp32:
    // 0=hist_real 1=hist_imag 2=cur_r 3=cur_i 4=conf 5=qW 6=qb 7=kW 8=kb 9=vW 10=vb
    const float* hr   = (const float*)d_in[0];
    const float* hi   = (const float*)d_in[1];
    const float* cr   = (const float*)d_in[2];
    const float* ci   = (const float*)d_in[3];
    const float* conf = (const float*)d_in[4];
    const float* qW   = (const float*)d_in[5];
    const float* qb   = (const float*)d_in[6];
    const float* kW   = (const float*)d_in[7];
    // d_in[8] = kb: softmax-invariant, unused
    const float* vW   = (const float*)d_in[9];
    const float* vb   = (const float*)d_in[10];
    float* out = (float*)d_out;   // out_size=2097152 fp32 = real part

    const float scale = 0.044194173824159216f;   // 512^-0.5
    bool dead = false;

    // 1) Q = concat(cur_r,cur_i) @ qW + qb -> g_Q        [4096,512], K=1024
    gemm_t<1, 0, 0, 0><<<dim3(DIM / 64, BT / 64), 128>>>(
        cr, ci, qW, DIM, qb, nullptr, 1.f, nullptr, nullptr, BT, DIM, DIM2);
    kl_stage(diag, "gemm1", &dead);
    if (dead) return;

    // 2) Qk' = (Q @ kW^T) * scale * conf[row] -> g_Qk    [4096,1024], K=512
    gemm_t<2, 1, 0, 1><<<dim3(DIM2 / 64, BT / 64), 128>>>(
        nullptr, nullptr, kW, 0, nullptr, conf, scale, nullptr, nullptr,
        BT, DIM2, DIM);
    kl_stage(diag, "gemm2", &dead);
    if (dead) return;

    // 3) warp-specialized online-softmax stream -> g_wH
    attn_f<<<BT, 256>>>(hr, hi);
    kl_stage(diag, "attn", &dead);
    if (dead) return;

    // 4) out = cur_r + 0.1 * (wH @ vW[:,0:512] + vb[0:512])   (real part)
    gemm_t<3, 0, 1, 2><<<dim3(DIM / 64, BT / 64), 128>>>(
        nullptr, nullptr, vW, DIM2, vb, nullptr, 1.f, cr, out, BT, DIM, DIM2);
    kl_stage(diag, "gemm4", &dead);
}

// round 12
// speedup vs baseline: 1.2138x; 1.2138x over previous
#include <cuda_runtime.h>
#include <cuda_bf16.h>
#include <cstdint>
#include <cstdio>

// Shapes (confirmed): B=4, T=1024, S=32, D=512; output = real part, fp32.
#define BT    4096
#define DIM   512
#define DIM2  1024
#define SLOTS 32

__device__ float g_W2[DIM2 * DIM2];   // qW @ kW^T   [1024 x 1024]
__device__ float g_b2[DIM2];          // kW @ qb     [1024]
__device__ float g_Qk[BT * DIM2];
__device__ float g_wH[BT * DIM2];

__device__ __forceinline__ unsigned tf32cvt(float f)
{
    unsigned r;
    asm("cvt.rna.tf32.f32 %0, %1;" : "=r"(r) : "f"(f));
    return r;
}
__device__ __forceinline__ int swA(int row, int col) { return col ^ (((row >> 2) & 3) << 3); }
__device__ __forceinline__ int swB(int col)          { return col ^ (((col >> 5) & 3) << 1); }

// ---------------------------------------------------------------------------
// TF32 GEMM, double-buffered: CTA tile 64(m) x 128(n), 256 threads (8 warps
// 2x4), warp tile 32x32 (2m x 4n m16n8k8), K-tile 16, reg prefetch + 2-stage
// smem, swizzled conflict-free fragment loads.
// CONCAT: 1 = A is concat(A=cur_r, A2=cur_i) rows of 512+512; 0 = plain [M,K]
// BMODE:  0 = B row-major [K x Bstride]; 1 = B is [N x K] (use B^T)
// EPI: 0 = C[m*N+n] = (acc + bias?[n]) * (rowscale? basescale*rowscale[m] : 1)
//      1 = real epilogue: C[m*512+n] = cur_r[m*512+n] + 0.1*(acc + bias[n])
// ---------------------------------------------------------------------------
template<int CONCAT, int BMODE, int EPI>
__global__ __launch_bounds__(256)
void gemm_db(const float* __restrict__ A, const float* __restrict__ A2,
             const float* __restrict__ B, int Bstride,
             const float* __restrict__ bias,
             const float* __restrict__ rowscale, float basescale,
             const float* __restrict__ cur_r,
             float* __restrict__ C,
             int M, int N, int K)
{
    __shared__ unsigned As[2][16][72];
    __shared__ unsigned Bs[2][16][136];

    const int tid  = threadIdx.x;
    const int lane = tid & 31;
    const int wid  = tid >> 5;
    const int wm   = wid & 1;
    const int wn   = wid >> 1;
    const int grp  = lane >> 2;
    const int tig  = lane & 3;
    const int bm   = blockIdx.y * 64;
    const int bn0  = blockIdx.x * 128;

    float acc[2][4][4];
#pragma unroll
    for (int a = 0; a < 2; a++)
#pragma unroll
        for (int b = 0; b < 4; b++)
#pragma unroll
            for (int c = 0; c < 4; c++) acc[a][b][c] = 0.f;

    // A loader: m = tid/4 (0..63), k = (tid%4)*4 ; one float4
    const int am  = tid >> 2;
    const int akk = (tid & 3) * 4;
    // B loader mode0: k = tid/16 (0..15), n = (tid%16)*8 ; two float4
    const int bkk = tid >> 4;
    const int bnn = (tid & 15) * 8;
    // B loader mode1: n = tid/2 (0..127), k = (tid%2)*8 ; two float4
    const int b1n = tid >> 1;
    const int b1k = (tid & 1) * 8;

    float4 aReg, bReg0, bReg1;

    auto ldg = [&](int k0) {
        {
            const long long m = bm + am;
            const long long k = k0 + akk;
            if (CONCAT) {
                aReg = (k < 512) ? *(const float4*)(A  + m * 512 + k)
                                 : *(const float4*)(A2 + m * 512 + (k - 512));
            } else {
                aReg = *(const float4*)(A + m * (long long)K + k);
            }
        }
        if (BMODE == 0) {
            const long long k = k0 + bkk;
            const long long n = bn0 + bnn;
            bReg0 = *(const float4*)(B + k * (long long)Bstride + n);
            bReg1 = *(const float4*)(B + k * (long long)Bstride + n + 4);
        } else {
            const long long n = bn0 + b1n;
            const long long k = k0 + b1k;
            bReg0 = *(const float4*)(B + n * (long long)K + k);
            bReg1 = *(const float4*)(B + n * (long long)K + k + 4);
        }
    };

    auto sts = [&](int buf) {
        const float av[4] = {aReg.x, aReg.y, aReg.z, aReg.w};
#pragma unroll
        for (int i = 0; i < 4; i++)
            As[buf][akk + i][swA(akk + i, am)] = tf32cvt(av[i]);
        const float bv[8] = {bReg0.x, bReg0.y, bReg0.z, bReg0.w,
                             bReg1.x, bReg1.y, bReg1.z, bReg1.w};
        if (BMODE == 0) {
#pragma unroll
            for (int i = 0; i < 8; i++)
                Bs[buf][bkk][swB(bnn + i)] = tf32cvt(bv[i]);
        } else {
#pragma unroll
            for (int i = 0; i < 8; i++)
                Bs[buf][b1k + i][swB(b1n)] = tf32cvt(bv[i]);
        }
    };

    const int nIter = K / 16;
    ldg(0);
    sts(0);
    if (nIter > 1) ldg(16);
    __syncthreads();

    for (int it = 0; it < nIter; it++) {
        const int buf = it & 1;
        if (it + 1 < nIter) sts(buf ^ 1);       // regs hold tile it+1
        if (it + 2 < nIter) ldg((it + 2) * 16); // prefetch tile it+2

#pragma unroll
        for (int k8 = 0; k8 < 16; k8 += 8) {
            unsigned af[2][4];
#pragma unroll
            for (int mt = 0; mt < 2; mt++) {
                const int r = wm * 32 + mt * 16 + grp;
                af[mt][0] = As[buf][k8 + tig    ][swA(k8 + tig,     r)];
                af[mt][1] = As[buf][k8 + tig    ][swA(k8 + tig,     r + 8)];
                af[mt][2] = As[buf][k8 + tig + 4][swA(k8 + tig + 4, r)];
                af[mt][3] = As[buf][k8 + tig + 4][swA(k8 + tig + 4, r + 8)];
            }
            unsigned bf[4][2];
#pragma unroll
            for (int nt = 0; nt < 4; nt++) {
                const int n = wn * 32 + nt * 8 + grp;
                bf[nt][0] = Bs[buf][k8 + tig    ][swB(n)];
                bf[nt][1] = Bs[buf][k8 + tig + 4][swB(n)];
            }
#pragma unroll
            for (int mt = 0; mt < 2; mt++)
#pragma unroll
                for (int nt = 0; nt < 4; nt++)
                    asm volatile(
                        "mma.sync.aligned.m16n8k8.row.col.f32.tf32.tf32.f32 "
                        "{%0,%1,%2,%3}, {%4,%5,%6,%7}, {%8,%9}, {%0,%1,%2,%3};"
                        : "+f"(acc[mt][nt][0]), "+f"(acc[mt][nt][1]),
                          "+f"(acc[mt][nt][2]), "+f"(acc[mt][nt][3])
                        : "r"(af[mt][0]), "r"(af[mt][1]),
                          "r"(af[mt][2]), "r"(af[mt][3]),
                          "r"(bf[nt][0]), "r"(bf[nt][1]));
        }
        __syncthreads();
    }

    // --- epilogue ---
#pragma unroll
    for (int mt = 0; mt < 2; mt++) {
#pragma unroll
        for (int half = 0; half < 2; half++) {
            const long long m = bm + wm * 32 + mt * 16 + grp + half * 8;
            float rs = 1.f;
            if (EPI == 0 && rowscale != nullptr)
                rs = basescale * __ldg(rowscale + m);
#pragma unroll
            for (int nt = 0; nt < 4; nt++) {
                const long long n = bn0 + wn * 32 + nt * 8 + 2 * tig;
                float v0 = acc[mt][nt][half * 2 + 0];
                float v1 = acc[mt][nt][half * 2 + 1];
                if (bias != nullptr) {
                    v0 += __ldg(bias + n);
                    v1 += __ldg(bias + n + 1);
                }
                if (EPI == 0) {
                    C[m * N + n]     = v0 * rs;
                    C[m * N + n + 1] = v1 * rs;
                } else {
                    const long long f = m * 512 + n;
                    C[f]     = __ldg(cur_r + f)     + 0.1f * v0;
                    C[f + 1] = __ldg(cur_r + f + 1) + 0.1f * v1;
                }
            }
        }
    }
}

// b2[n] = sum_k kW[n,k] * qb[k]   (one warp per n)
__global__ __launch_bounds__(256)
void bias2_k(const float* __restrict__ kW, const float* __restrict__ qb,
             float* __restrict__ b2)
{
    const int n    = blockIdx.x * 8 + (threadIdx.x >> 5);
    const int lane = threadIdx.x & 31;
    const float* row = kW + (long long)n * 512;
    float s = 0.f;
#pragma unroll
    for (int k = lane * 4; k < 512; k += 128) {
        const float4 v = *(const float4*)(row + k);
        const float4 q = *(const float4*)(qb + k);
        s += v.x * q.x + v.y * q.y + v.z * q.z + v.w * q.w;
    }
#pragma unroll
    for (int o = 16; o; o >>= 1) s += __shfl_xor_sync(0xffffffffu, s, o);
    if (lane == 0) b2[n] = s;
}

// ---------------------------------------------------------------------------
// Warp-specialized streaming attention (unchanged, known-good).
// ---------------------------------------------------------------------------
__global__ __launch_bounds__(256)
void attn_f(const float* __restrict__ hr, const float* __restrict__ hi)
{
    __shared__ __align__(16) float shQ[DIM2];
    __shared__ __align__(16) float shAcc[8][8][32][4];
    __shared__ float shM[8], shL[8];

    const int bt = blockIdx.x;
    const int w  = threadIdx.x >> 5;
    const int c  = threadIdx.x & 31;

    {
        const float* q = g_Qk + (size_t)bt * DIM2;
        *(float4*)&shQ[threadIdx.x * 4] = *(const float4*)(q + threadIdx.x * 4);
    }
    __syncthreads();

    const float* pr = hr + (size_t)bt * (SLOTS * 512) + 4 * c;
    const float* pi = hi + (size_t)bt * (SLOTS * 512) + 4 * c;

    float m = -1e30f, l = 0.f;
    float4 acc[8];
#pragma unroll
    for (int k = 0; k < 8; k++) acc[k] = make_float4(0.f, 0.f, 0.f, 0.f);

#pragma unroll
    for (int si = 0; si < 4; si++) {
        const int s = w + si * 8;
        float4 h[8];
#pragma unroll
        for (int k = 0; k < 4; k++)
            h[k] = *(const float4*)(pr + (size_t)s * 512 + k * 128);
#pragma unroll
        for (int k = 0; k < 4; k++)
            h[k + 4] = *(const float4*)(pi + (size_t)s * 512 + k * 128);

        float p = 0.f;
#pragma unroll
        for (int k = 0; k < 8; k++) {
            const float4 q = *(const float4*)&shQ[k * 128 + 4 * c];
            p += h[k].x * q.x + h[k].y * q.y + h[k].z * q.z + h[k].w * q.w;
        }
#pragma unroll
        for (int off = 16; off; off >>= 1)
            p += __shfl_xor_sync(0xffffffffu, p, off);

        const float mn = fmaxf(m, p);
        const float cf = __expf(m - mn);
        const float pw = __expf(p - mn);
        l = l * cf + pw;
#pragma unroll
        for (int k = 0; k < 8; k++) {
            acc[k].x = acc[k].x * cf + pw * h[k].x;
            acc[k].y = acc[k].y * cf + pw * h[k].y;
            acc[k].z = acc[k].z * cf + pw * h[k].z;
            acc[k].w = acc[k].w * cf + pw * h[k].w;
        }
        m = mn;
    }

    if (c == 0) { shM[w] = m; shL[w] = l; }
    __syncthreads();
    float M = -1e30f;
#pragma unroll
    for (int i = 0; i < 8; i++) M = fmaxf(M, shM[i]);
    float L = 0.f;
#pragma unroll
    for (int i = 0; i < 8; i++) L += shL[i] * __expf(shM[i] - M);
    const float myE = __expf(m - M);

#pragma unroll
    for (int k = 0; k < 8; k++) {
        float4 v = acc[k];
        v.x *= myE; v.y *= myE; v.z *= myE; v.w *= myE;
        *(float4*)&shAcc[w][k][c][0] = v;
    }
    __syncthreads();

    const float invL = 1.f / L;
    float4 sum = make_float4(0.f, 0.f, 0.f, 0.f);
#pragma unroll
    for (int sw = 0; sw < 8; sw++) {
        const float4 v = *(const float4*)&shAcc[sw][w][c][0];
        sum.x += v.x; sum.y += v.y; sum.z += v.z; sum.w += v.w;
    }
    sum.x *= invL; sum.y *= invL; sum.z *= invL; sum.w *= invL;
    *(float4*)&g_wH[(size_t)bt * DIM2 + w * 128 + 4 * c] = sum;
}

// ---------------------------------------------------------------------------
// Host-side staged diagnostics (only on the non-captured correctness call).
// ---------------------------------------------------------------------------
static bool kl_capturing()
{
    cudaStreamCaptureStatus st = cudaStreamCaptureStatusNone;
    cudaError_t e = cudaStreamIsCapturing((cudaStream_t)0, &st);
    if (e != cudaSuccess) { (void)cudaGetLastError(); return true; }
    return st != cudaStreamCaptureStatusNone;
}
static cudaError_t kl_poll()
{
    cudaEvent_t ev;
    if (cudaEventCreateWithFlags(&ev, cudaEventDisableTiming) != cudaSuccess)
        return cudaGetLastError();
    cudaEventRecord(ev, (cudaStream_t)0);
    cudaError_t e;
    do { e = cudaEventQuery(ev); } while (e == cudaErrorNotReady);
    cudaEventDestroy(ev);
    return e;
}
static void kl_stage(bool diag, const char* name, bool* dead)
{
    if (!diag || *dead) return;
    cudaError_t e = kl_poll();
    if (e != cudaSuccess) {
        fprintf(stderr, "[KLDIAG] stage %s -> %s\n", name, cudaGetErrorString(e));
        *dead = true;
    }
}

// ---------------------------------------------------------------------------
extern "C" void kernel_launch(void* const* d_in, const int* in_sizes, int n_in,
                              void* d_out, int out_size)
{
    const bool diag = !kl_capturing();
    if (n_in < 11) return;

    // Confirmed insertion order, all fp32:
    // 0=hist_real 1=hist_imag 2=cur_r 3=cur_i 4=conf 5=qW 6=qb 7=kW 8=kb 9=vW 10=vb
    const float* hr   = (const float*)d_in[0];
    const float* hi   = (const float*)d_in[1];
    const float* cr   = (const float*)d_in[2];
    const float* ci   = (const float*)d_in[3];
    const float* conf = (const float*)d_in[4];
    const float* qW   = (const float*)d_in[5];
    const float* qb   = (const float*)d_in[6];
    const float* kW   = (const float*)d_in[7];
    // d_in[8] = kb: softmax-invariant, unused
    const float* vW   = (const float*)d_in[9];
    const float* vb   = (const float*)d_in[10];
    float* out = (float*)d_out;   // out_size fp32 elements = real part

    // Resolve device-global scratch addresses (pure lookup, capture-safe).
    float *pW2 = nullptr, *pB2 = nullptr, *pQk = nullptr, *pwH = nullptr;
    cudaGetSymbolAddress((void**)&pW2, g_W2);
    cudaGetSymbolAddress((void**)&pB2, g_b2);
    cudaGetSymbolAddress((void**)&pQk, g_Qk);
    cudaGetSymbolAddress((void**)&pwH, g_wH);
    if (!pW2 || !pB2 || !pQk || !pwH) return;

    const float scale = 0.044194173824159216f;   // 512^-0.5
    bool dead = false;

    // 1a) W2 = qW @ kW^T   [1024,1024], K=512
    gemm_db<0, 1, 0><<<dim3(DIM2 / 128, DIM2 / 64), 256>>>(
        qW, nullptr, kW, 0, nullptr, nullptr, 1.f, nullptr, pW2,
        DIM2, DIM2, DIM);
    // 1b) b2 = kW @ qb
    bias2_k<<<DIM2 / 8, 256>>>(kW, qb, pB2);
    kl_stage(diag, "w2", &dead);
    if (dead) return;

    // 2) Qk = (cur2 @ W2 + b2) * scale * conf[m]   [4096,1024], K=1024
    gemm_db<1, 0, 0><<<dim3(DIM2 / 128, BT / 64), 256>>>(
        cr, ci, pW2, DIM2, pB2, conf, scale, nullptr, pQk, BT, DIM2, DIM2);
    kl_stage(diag, "qk", &dead);
    if (dead) return;

    // 3) warp-specialized online-softmax stream -> g_wH
    attn_f<<<BT, 256>>>(hr, hi);
    kl_stage(diag, "attn", &dead);
    if (dead) return;

    // 4) out = cur_r + 0.1 * (wH @ vW[:,0:512] + vb[0:512])   (real part)
    gemm_db<0, 0, 1><<<dim3(DIM / 128, BT / 64), 256>>>(
        pwH, nullptr, vW, DIM2, vb, nullptr, 1.f, cr, out, BT, DIM, DIM2);
    kl_stage(diag, "gemm4", &dead);
}

// round 13
// speedup vs baseline: 1.3205x; 1.0879x over previous
#include <cuda_runtime.h>
#include <cuda_bf16.h>
#include <cstdint>
#include <cstdio>

// Shapes (confirmed): B=4, T=1024, S=32, D=512; output = real part, fp32.
#define BT    4096
#define DIM   512
#define DIM2  1024
#define SLOTS 32

__device__ float g_W2[DIM2 * DIM2];   // qW @ kW^T   [1024 x 1024]
__device__ float g_b2[DIM2];          // kW @ qb     [1024]
__device__ float g_Qk[BT * DIM2];
__device__ float g_wH[BT * DIM2];

__device__ __forceinline__ unsigned tf32cvt(float f)
{
    unsigned r;
    asm("cvt.rna.tf32.f32 %0, %1;" : "=r"(r) : "f"(f));
    return r;
}
__device__ __forceinline__ int swA(int row, int col) { return col ^ (((row >> 2) & 3) << 3); }
__device__ __forceinline__ int swB(int col)          { return col ^ (((col >> 5) & 3) << 1); }

// ---------------------------------------------------------------------------
// TF32 GEMM, double-buffered (unchanged from R12 WIN): CTA 64x128, 256 thr,
// warp tile 32x32, K-tile 16, reg prefetch + 2-stage smem, swizzled smem.
// CONCAT: 1 = A is concat(A=cur_r, A2=cur_i) rows of 512+512; 0 = plain [M,K]
// BMODE:  0 = B row-major [K x Bstride]; 1 = B is [N x K] (use B^T)
// EPI: 0 = C = (acc + bias?) * (rowscale? basescale*rowscale[m] : 1)
//      1 = real epilogue: C[m*512+n] = cur_r[m*512+n] + 0.1*(acc + bias[n])
// ---------------------------------------------------------------------------
template<int CONCAT, int BMODE, int EPI>
__global__ __launch_bounds__(256)
void gemm_db(const float* __restrict__ A, const float* __restrict__ A2,
             const float* __restrict__ B, int Bstride,
             const float* __restrict__ bias,
             const float* __restrict__ rowscale, float basescale,
             const float* __restrict__ cur_r,
             float* __restrict__ C,
             int M, int N, int K)
{
    __shared__ unsigned As[2][16][72];
    __shared__ unsigned Bs[2][16][136];

    const int tid  = threadIdx.x;
    const int lane = tid & 31;
    const int wid  = tid >> 5;
    const int wm   = wid & 1;
    const int wn   = wid >> 1;
    const int grp  = lane >> 2;
    const int tig  = lane & 3;
    const int bm   = blockIdx.y * 64;
    const int bn0  = blockIdx.x * 128;

    float acc[2][4][4];
#pragma unroll
    for (int a = 0; a < 2; a++)
#pragma unroll
        for (int b = 0; b < 4; b++)
#pragma unroll
            for (int c = 0; c < 4; c++) acc[a][b][c] = 0.f;

    const int am  = tid >> 2;
    const int akk = (tid & 3) * 4;
    const int bkk = tid >> 4;
    const int bnn = (tid & 15) * 8;
    const int b1n = tid >> 1;
    const int b1k = (tid & 1) * 8;

    float4 aReg, bReg0, bReg1;

    auto ldg = [&](int k0) {
        {
            const long long m = bm + am;
            const long long k = k0 + akk;
            if (CONCAT) {
                aReg = (k < 512) ? *(const float4*)(A  + m * 512 + k)
                                 : *(const float4*)(A2 + m * 512 + (k - 512));
            } else {
                aReg = *(const float4*)(A + m * (long long)K + k);
            }
        }
        if (BMODE == 0) {
            const long long k = k0 + bkk;
            const long long n = bn0 + bnn;
            bReg0 = *(const float4*)(B + k * (long long)Bstride + n);
            bReg1 = *(const float4*)(B + k * (long long)Bstride + n + 4);
        } else {
            const long long n = bn0 + b1n;
            const long long k = k0 + b1k;
            bReg0 = *(const float4*)(B + n * (long long)K + k);
            bReg1 = *(const float4*)(B + n * (long long)K + k + 4);
        }
    };

    auto sts = [&](int buf) {
        const float av[4] = {aReg.x, aReg.y, aReg.z, aReg.w};
#pragma unroll
        for (int i = 0; i < 4; i++)
            As[buf][akk + i][swA(akk + i, am)] = tf32cvt(av[i]);
        const float bv[8] = {bReg0.x, bReg0.y, bReg0.z, bReg0.w,
                             bReg1.x, bReg1.y, bReg1.z, bReg1.w};
        if (BMODE == 0) {
#pragma unroll
            for (int i = 0; i < 8; i++)
                Bs[buf][bkk][swB(bnn + i)] = tf32cvt(bv[i]);
        } else {
#pragma unroll
            for (int i = 0; i < 8; i++)
                Bs[buf][b1k + i][swB(b1n)] = tf32cvt(bv[i]);
        }
    };

    const int nIter = K / 16;
    ldg(0);
    sts(0);
    if (nIter > 1) ldg(16);
    __syncthreads();

    for (int it = 0; it < nIter; it++) {
        const int buf = it & 1;
        if (it + 1 < nIter) sts(buf ^ 1);
        if (it + 2 < nIter) ldg((it + 2) * 16);

#pragma unroll
        for (int k8 = 0; k8 < 16; k8 += 8) {
            unsigned af[2][4];
#pragma unroll
            for (int mt = 0; mt < 2; mt++) {
                const int r = wm * 32 + mt * 16 + grp;
                af[mt][0] = As[buf][k8 + tig    ][swA(k8 + tig,     r)];
                af[mt][1] = As[buf][k8 + tig    ][swA(k8 + tig,     r + 8)];
                af[mt][2] = As[buf][k8 + tig + 4][swA(k8 + tig + 4, r)];
                af[mt][3] = As[buf][k8 + tig + 4][swA(k8 + tig + 4, r + 8)];
            }
            unsigned bf[4][2];
#pragma unroll
            for (int nt = 0; nt < 4; nt++) {
                const int n = wn * 32 + nt * 8 + grp;
                bf[nt][0] = Bs[buf][k8 + tig    ][swB(n)];
                bf[nt][1] = Bs[buf][k8 + tig + 4][swB(n)];
            }
#pragma unroll
            for (int mt = 0; mt < 2; mt++)
#pragma unroll
                for (int nt = 0; nt < 4; nt++)
                    asm volatile(
                        "mma.sync.aligned.m16n8k8.row.col.f32.tf32.tf32.f32 "
                        "{%0,%1,%2,%3}, {%4,%5,%6,%7}, {%8,%9}, {%0,%1,%2,%3};"
                        : "+f"(acc[mt][nt][0]), "+f"(acc[mt][nt][1]),
                          "+f"(acc[mt][nt][2]), "+f"(acc[mt][nt][3])
                        : "r"(af[mt][0]), "r"(af[mt][1]),
                          "r"(af[mt][2]), "r"(af[mt][3]),
                          "r"(bf[nt][0]), "r"(bf[nt][1]));
        }
        __syncthreads();
    }

#pragma unroll
    for (int mt = 0; mt < 2; mt++) {
#pragma unroll
        for (int half = 0; half < 2; half++) {
            const long long m = bm + wm * 32 + mt * 16 + grp + half * 8;
            float rs = 1.f;
            if (EPI == 0 && rowscale != nullptr)
                rs = basescale * __ldg(rowscale + m);
#pragma unroll
            for (int nt = 0; nt < 4; nt++) {
                const long long n = bn0 + wn * 32 + nt * 8 + 2 * tig;
                float v0 = acc[mt][nt][half * 2 + 0];
                float v1 = acc[mt][nt][half * 2 + 1];
                if (bias != nullptr) {
                    v0 += __ldg(bias + n);
                    v1 += __ldg(bias + n + 1);
                }
                if (EPI == 0) {
                    C[m * N + n]     = v0 * rs;
                    C[m * N + n + 1] = v1 * rs;
                } else {
                    const long long f = m * 512 + n;
                    C[f]     = __ldg(cur_r + f)     + 0.1f * v0;
                    C[f + 1] = __ldg(cur_r + f + 1) + 0.1f * v1;
                }
            }
        }
    }
}

// b2[n] = sum_k kW[n,k] * qb[k]   (one warp per n)
__global__ __launch_bounds__(256)
void bias2_k(const float* __restrict__ kW, const float* __restrict__ qb,
             float* __restrict__ b2)
{
    const int n    = blockIdx.x * 8 + (threadIdx.x >> 5);
    const int lane = threadIdx.x & 31;
    const float* row = kW + (long long)n * 512;
    float s = 0.f;
#pragma unroll
    for (int k = lane * 4; k < 512; k += 128) {
        const float4 v = *(const float4*)(row + k);
        const float4 q = *(const float4*)(qb + k);
        s += v.x * q.x + v.y * q.y + v.z * q.z + v.w * q.w;
    }
#pragma unroll
    for (int o = 16; o; o >>= 1) s += __shfl_xor_sync(0xffffffffu, s, o);
    if (lane == 0) b2[n] = s;
}

// ---------------------------------------------------------------------------
// Two-phase attention: low-register, high-occupancy.
// Phase 1: warp w -> scores of slots {w,w+8,w+16,w+24} (h streamed, not held).
// Exact softmax over the 32 scores in smem.
// Phase 2: thread owns 4 output cols, streams 32 rows: acc += w_s * h.
// ---------------------------------------------------------------------------
__global__ __launch_bounds__(256)
void attn_2p(const float* __restrict__ hr, const float* __restrict__ hi)
{
    __shared__ __align__(16) float shQ[DIM2];
    __shared__ float shS[SLOTS];
    __shared__ float shW[SLOTS];

    const int bt  = blockIdx.x;
    const int tid = threadIdx.x;
    const int w   = tid >> 5;
    const int c   = tid & 31;

    *(float4*)&shQ[tid * 4] = *(const float4*)(g_Qk + (size_t)bt * DIM2 + tid * 4);
    __syncthreads();

    const float* baseR = hr + (size_t)bt * (SLOTS * 512);
    const float* baseI = hi + (size_t)bt * (SLOTS * 512);

    // --- Phase 1: scores ---
#pragma unroll
    for (int si = 0; si < 4; si++) {
        const int s = w + si * 8;
        const float* prow = baseR + (size_t)s * 512 + 4 * c;
        const float* irow = baseI + (size_t)s * 512 + 4 * c;
        float p = 0.f;
#pragma unroll
        for (int k = 0; k < 4; k++) {
            const float4 h = *(const float4*)(prow + k * 128);
            const float4 q = *(const float4*)&shQ[k * 128 + 4 * c];
            p += h.x * q.x + h.y * q.y + h.z * q.z + h.w * q.w;
        }
#pragma unroll
        for (int k = 0; k < 4; k++) {
            const float4 h = *(const float4*)(irow + k * 128);
            const float4 q = *(const float4*)&shQ[512 + k * 128 + 4 * c];
            p += h.x * q.x + h.y * q.y + h.z * q.z + h.w * q.w;
        }
#pragma unroll
        for (int off = 16; off; off >>= 1)
            p += __shfl_xor_sync(0xffffffffu, p, off);
        if (c == 0) shS[s] = p;
    }
    __syncthreads();

    // --- softmax weights (exact, global max) ---
    if (tid < SLOTS) {
        float m = -1e30f;
#pragma unroll
        for (int i = 0; i < SLOTS; i++) m = fmaxf(m, shS[i]);
        shW[tid] = __expf(shS[tid] - m);
    }
    __syncthreads();
    float L = 0.f;
#pragma unroll
    for (int i = 0; i < SLOTS; i++) L += shW[i];
    const float invL = 1.f / L;

    // --- Phase 2: weighted sum; thread owns cols [tid*4, +4) ---
    const int j = tid * 4;
    const float* src = (j < 512) ? (baseR + j) : (baseI + (j - 512));
    float4 acc = make_float4(0.f, 0.f, 0.f, 0.f);
#pragma unroll 8
    for (int s = 0; s < SLOTS; s++) {
        const float4 h = *(const float4*)(src + (size_t)s * 512);
        const float ws = shW[s];
        acc.x += ws * h.x;
        acc.y += ws * h.y;
        acc.z += ws * h.z;
        acc.w += ws * h.w;
    }
    acc.x *= invL; acc.y *= invL; acc.z *= invL; acc.w *= invL;
    *(float4*)&g_wH[(size_t)bt * DIM2 + j] = acc;
}

// ---------------------------------------------------------------------------
// Host-side staged diagnostics (only on the non-captured correctness call).
// ---------------------------------------------------------------------------
static bool kl_capturing()
{
    cudaStreamCaptureStatus st = cudaStreamCaptureStatusNone;
    cudaError_t e = cudaStreamIsCapturing((cudaStream_t)0, &st);
    if (e != cudaSuccess) { (void)cudaGetLastError(); return true; }
    return st != cudaStreamCaptureStatusNone;
}
static cudaError_t kl_poll()
{
    cudaEvent_t ev;
    if (cudaEventCreateWithFlags(&ev, cudaEventDisableTiming) != cudaSuccess)
        return cudaGetLastError();
    cudaEventRecord(ev, (cudaStream_t)0);
    cudaError_t e;
    do { e = cudaEventQuery(ev); } while (e == cudaErrorNotReady);
    cudaEventDestroy(ev);
    return e;
}
static void kl_stage(bool diag, const char* name, bool* dead)
{
    if (!diag || *dead) return;
    cudaError_t e = kl_poll();
    if (e != cudaSuccess) {
        fprintf(stderr, "[KLDIAG] stage %s -> %s\n", name, cudaGetErrorString(e));
        *dead = true;
    }
}

// ---------------------------------------------------------------------------
extern "C" void kernel_launch(void* const* d_in, const int* in_sizes, int n_in,
                              void* d_out, int out_size)
{
    const bool diag = !kl_capturing();
    if (n_in < 11) return;

    // Confirmed insertion order, all fp32:
    // 0=hist_real 1=hist_imag 2=cur_r 3=cur_i 4=conf 5=qW 6=qb 7=kW 8=kb 9=vW 10=vb
    const float* hr   = (const float*)d_in[0];
    const float* hi   = (const float*)d_in[1];
    const float* cr   = (const float*)d_in[2];
    const float* ci   = (const float*)d_in[3];
    const float* conf = (const float*)d_in[4];
    const float* qW   = (const float*)d_in[5];
    const float* qb   = (const float*)d_in[6];
    const float* kW   = (const float*)d_in[7];
    // d_in[8] = kb: softmax-invariant, unused
    const float* vW   = (const float*)d_in[9];
    const float* vb   = (const float*)d_in[10];
    float* out = (float*)d_out;   // out_size fp32 elements = real part

    float *pW2 = nullptr, *pB2 = nullptr, *pQk = nullptr, *pwH = nullptr;
    cudaGetSymbolAddress((void**)&pW2, g_W2);
    cudaGetSymbolAddress((void**)&pB2, g_b2);
    cudaGetSymbolAddress((void**)&pQk, g_Qk);
    cudaGetSymbolAddress((void**)&pwH, g_wH);
    if (!pW2 || !pB2 || !pQk || !pwH) return;

    const float scale = 0.044194173824159216f;   // 512^-0.5
    bool dead = false;

    // 1a) W2 = qW @ kW^T   [1024,1024], K=512
    gemm_db<0, 1, 0><<<dim3(DIM2 / 128, DIM2 / 64), 256>>>(
        qW, nullptr, kW, 0, nullptr, nullptr, 1.f, nullptr, pW2,
        DIM2, DIM2, DIM);
    // 1b) b2 = kW @ qb
    bias2_k<<<DIM2 / 8, 256>>>(kW, qb, pB2);
    kl_stage(diag, "w2", &dead);
    if (dead) return;

    // 2) Qk = (cur2 @ W2 + b2) * scale * conf[m]   [4096,1024], K=1024
    gemm_db<1, 0, 0><<<dim3(DIM2 / 128, BT / 64), 256>>>(
        cr, ci, pW2, DIM2, pB2, conf, scale, nullptr, pQk, BT, DIM2, DIM2);
    kl_stage(diag, "qk", &dead);
    if (dead) return;

    // 3) two-phase softmax attention -> g_wH
    attn_2p<<<BT, 256>>>(hr, hi);
    kl_stage(diag, "attn", &dead);
    if (dead) return;

    // 4) out = cur_r + 0.1 * (wH @ vW[:,0:512] + vb[0:512])   (real part)
    gemm_db<0, 0, 1><<<dim3(DIM / 128, BT / 64), 256>>>(
        pwH, nullptr, vW, DIM2, vb, nullptr, 1.f, cr, out, BT, DIM, DIM2);
    kl_stage(diag, "gemm4", &dead);
}